// round 1
// baseline (speedup 1.0000x reference)
#include <cuda_runtime.h>
#include <math.h>

#define BB 8
#define NLEN 512
#define CDIM 128
#define NNE (NLEN*NLEN)          // 262144 = 2^18
#define KSEL 43690               // NNE//6
#define FSCALE 0.08838834764831845f
#define CAP 4096

// ---------------- scratch (static device globals; no allocation) -------------
static __device__ float g_E [BB*NNE];
static __device__ float g_Ch[BB*NNE];
static __device__ float g_V [BB*NNE];
static __device__ float g_L [BB*NNE];
static __device__ float g_W [BB*NNE];
static __device__ float g_sq[BB*NLEN];
static __device__ float g_mu[BB*NLEN];
static __device__ float g_ds[BB*NLEN];
static __device__ unsigned int g_hist[3*BB*256];
static __device__ unsigned int g_cnt[BB];
struct Sel { unsigned int hi; unsigned int need; };
static __device__ Sel g_sel[BB];
static __device__ unsigned long long g_cand[BB*CAP];
static __device__ unsigned long long g_cut[BB];

__device__ __forceinline__ unsigned int ford(float f) {
    unsigned int u = __float_as_uint(f);
    return (u & 0x80000000u) ? ~u : (u | 0x80000000u);   // monotone float->uint
}

// ---------------- zero per-iteration state ----------------------------------
__global__ void zero_kernel() {
    int t = blockIdx.x * blockDim.x + threadIdx.x;
    if (t < 3*BB*256) g_hist[t] = 0u;
    if (t < BB)       g_cnt[t]  = 0u;
}

// ---------------- per-row stats: sq = sum x^2, mu, ds = ||x - mu|| ----------
__global__ void stats_kernel(const float* __restrict__ x) {
    int row  = blockIdx.x * 8 + (threadIdx.x >> 5);     // 4096 rows
    int lane = threadIdx.x & 31;
    const float* xr = x + (size_t)row * CDIM;
    float v[4]; float s = 0.f, ss = 0.f;
#pragma unroll
    for (int i = 0; i < 4; i++) {
        v[i] = xr[lane + 32*i];
        s  += v[i];
        ss += v[i]*v[i];
    }
#pragma unroll
    for (int o = 16; o; o >>= 1) {
        s  += __shfl_xor_sync(0xffffffffu, s,  o);
        ss += __shfl_xor_sync(0xffffffffu, ss, o);
    }
    float mu = s * (1.0f/CDIM);
    float cs = 0.f;
#pragma unroll
    for (int i = 0; i < 4; i++) { float d = v[i]-mu; cs += d*d; }
#pragma unroll
    for (int o = 16; o; o >>= 1) cs += __shfl_xor_sync(0xffffffffu, cs, o);
    if (lane == 0) { g_mu[row] = mu; g_sq[row] = ss; g_ds[row] = sqrtf(cs); }
}

// ---------------- E / Ch / V tiles (64x64, 256 thr, 4x4 micro) --------------
__global__ void ecv_kernel(const float* __restrict__ x) {
    __shared__ float Xn[64][65];
    __shared__ float Xm[64][65];
    int b  = blockIdx.z;
    int i0 = blockIdx.y * 64, j0 = blockIdx.x * 64;
    int t  = threadIdx.x;
    int tx = t & 15, ty = t >> 4;
    const float* xb = x + (size_t)b * NLEN * CDIM;

    float g[4][4], ch[4][4];
#pragma unroll
    for (int i = 0; i < 4; i++)
#pragma unroll
        for (int j = 0; j < 4; j++) { g[i][j] = 0.f; ch[i][j] = 0.f; }

    for (int ph = 0; ph < 2; ph++) {
        int cbase = ph * 64;
#pragma unroll
        for (int it = 0; it < 4; it++) {
            int idx = t + 256*it;            // 0..1023 float4 slots
            int r   = idx >> 4;              // 0..63
            int c4  = (idx & 15) * 4;        // 0..60
            float4 a = *(const float4*)&xb[(size_t)(i0+r)*CDIM + cbase + c4];
            Xn[c4+0][r] = a.x; Xn[c4+1][r] = a.y; Xn[c4+2][r] = a.z; Xn[c4+3][r] = a.w;
            float4 m = *(const float4*)&xb[(size_t)(j0+r)*CDIM + cbase + c4];
            Xm[c4+0][r] = m.x; Xm[c4+1][r] = m.y; Xm[c4+2][r] = m.z; Xm[c4+3][r] = m.w;
        }
        __syncthreads();
#pragma unroll 4
        for (int c = 0; c < 64; c++) {
            float a[4], bv[4];
#pragma unroll
            for (int q = 0; q < 4; q++) { a[q] = Xn[c][ty*4+q]; bv[q] = Xm[c][tx*4+q]; }
#pragma unroll
            for (int i = 0; i < 4; i++)
#pragma unroll
                for (int j = 0; j < 4; j++) {
                    g[i][j]  = fmaf(a[i], bv[j], g[i][j]);
                    ch[i][j] = fmaxf(ch[i][j], fabsf(a[i] - bv[j]));
                }
        }
        __syncthreads();
    }

    int ib = b*NLEN + i0 + ty*4;
    int jb = b*NLEN + j0 + tx*4;
    float sqi[4], mui[4], dsi[4], sqj[4], muj[4], dsj[4];
#pragma unroll
    for (int q = 0; q < 4; q++) {
        sqi[q] = g_sq[ib+q]; mui[q] = g_mu[ib+q]; dsi[q] = g_ds[ib+q];
        sqj[q] = g_sq[jb+q]; muj[q] = g_mu[jb+q]; dsj[q] = g_ds[jb+q];
    }
#pragma unroll
    for (int i = 0; i < 4; i++) {
        float4 e4, h4, v4;
        float ebuf[4], vbuf[4];
#pragma unroll
        for (int j = 0; j < 4; j++) {
            float d2 = sqi[i] + sqj[j] - 2.0f * g[i][j];
            ebuf[j] = sqrtf(fmaxf(d2, 0.0f));
            float cov = g[i][j] - (float)CDIM * mui[i] * muj[j];
            float vv  = cov / (dsi[i] * dsj[j]);
            vbuf[j] = fminf(fmaxf(vv, -1.0f), 1.0f);
        }
        e4 = make_float4(ebuf[0], ebuf[1], ebuf[2], ebuf[3]);
        h4 = make_float4(ch[i][0], ch[i][1], ch[i][2], ch[i][3]);
        v4 = make_float4(vbuf[0], vbuf[1], vbuf[2], vbuf[3]);
        size_t off = (size_t)b*NNE + (size_t)(i0 + ty*4 + i)*NLEN + j0 + tx*4;
        *(float4*)&g_E [off] = e4;
        *(float4*)&g_Ch[off] = h4;
        *(float4*)&g_V [off] = v4;
    }
}

// ---------------- GEMM NT: L[n,m] = sum_k E[n,k] * Ch[m,k] ------------------
__global__ void gemm_nt_kernel() {
    __shared__ float As[16][65];
    __shared__ float Bs[16][65];
    int b  = blockIdx.z;
    const float* A  = g_E  + (size_t)b*NNE;
    const float* Bm = g_Ch + (size_t)b*NNE;
    float*       Cm = g_L  + (size_t)b*NNE;
    int i0 = blockIdx.y * 64, j0 = blockIdx.x * 64;
    int t  = threadIdx.x, tx = t & 15, ty = t >> 4;
    int lr = t >> 2, lc = (t & 3) * 4;

    float acc[4][4];
#pragma unroll
    for (int i = 0; i < 4; i++)
#pragma unroll
        for (int j = 0; j < 4; j++) acc[i][j] = 0.f;

    for (int kb = 0; kb < NLEN; kb += 16) {
        float4 av = *(const float4*)&A [(size_t)(i0+lr)*NLEN + kb + lc];
        float4 bv = *(const float4*)&Bm[(size_t)(j0+lr)*NLEN + kb + lc];
        As[lc+0][lr]=av.x; As[lc+1][lr]=av.y; As[lc+2][lr]=av.z; As[lc+3][lr]=av.w;
        Bs[lc+0][lr]=bv.x; Bs[lc+1][lr]=bv.y; Bs[lc+2][lr]=bv.z; Bs[lc+3][lr]=bv.w;
        __syncthreads();
#pragma unroll
        for (int kk = 0; kk < 16; kk++) {
            float a[4], bb[4];
#pragma unroll
            for (int q = 0; q < 4; q++) { a[q] = As[kk][ty*4+q]; bb[q] = Bs[kk][tx*4+q]; }
#pragma unroll
            for (int i = 0; i < 4; i++)
#pragma unroll
                for (int j = 0; j < 4; j++) acc[i][j] = fmaf(a[i], bb[j], acc[i][j]);
        }
        __syncthreads();
    }
#pragma unroll
    for (int i = 0; i < 4; i++) {
        float4 r = make_float4(acc[i][0], acc[i][1], acc[i][2], acc[i][3]);
        *(float4*)&Cm[(size_t)(i0 + ty*4 + i)*NLEN + j0 + tx*4] = r;
    }
}

// ---------------- GEMM NN: W[n,k] = sum_m attn[n,m] * V[m,k] ----------------
__global__ void gemm_nn_kernel() {
    __shared__ float As[16][65];
    __shared__ float Bs[16][65];
    int b  = blockIdx.z;
    const float* A  = g_L + (size_t)b*NNE;
    const float* Bm = g_V + (size_t)b*NNE;
    float*       Cm = g_W + (size_t)b*NNE;
    int i0 = blockIdx.y * 64, j0 = blockIdx.x * 64;
    int t  = threadIdx.x, tx = t & 15, ty = t >> 4;
    int lr = t >> 2, lc = (t & 3) * 4;
    int bk = t >> 6, bj = t & 63;                 // B tile loader

    float acc[4][4];
#pragma unroll
    for (int i = 0; i < 4; i++)
#pragma unroll
        for (int j = 0; j < 4; j++) acc[i][j] = 0.f;

    for (int kb = 0; kb < NLEN; kb += 16) {
        float4 av = *(const float4*)&A[(size_t)(i0+lr)*NLEN + kb + lc];
        As[lc+0][lr]=av.x; As[lc+1][lr]=av.y; As[lc+2][lr]=av.z; As[lc+3][lr]=av.w;
#pragma unroll
        for (int u = 0; u < 4; u++) {
            int kk = bk + u*4;
            Bs[kk][bj] = Bm[(size_t)(kb+kk)*NLEN + j0 + bj];
        }
        __syncthreads();
#pragma unroll
        for (int kk = 0; kk < 16; kk++) {
            float a[4], bb[4];
#pragma unroll
            for (int q = 0; q < 4; q++) { a[q] = As[kk][ty*4+q]; bb[q] = Bs[kk][tx*4+q]; }
#pragma unroll
            for (int i = 0; i < 4; i++)
#pragma unroll
                for (int j = 0; j < 4; j++) acc[i][j] = fmaf(a[i], bb[j], acc[i][j]);
        }
        __syncthreads();
    }
#pragma unroll
    for (int i = 0; i < 4; i++) {
        float4 r = make_float4(acc[i][0], acc[i][1], acc[i][2], acc[i][3]);
        *(float4*)&Cm[(size_t)(i0 + ty*4 + i)*NLEN + j0 + tx*4] = r;
    }
}

// ---------------- row softmax of L*SCALE (in place) -------------------------
__global__ void softmax_kernel() {
    __shared__ float red[128];
    int row = blockIdx.x;                          // 0..4095
    float* p = g_L + (size_t)row * NLEN;
    int t = threadIdx.x;
    float v[4]; float mx = -3.4e38f;
#pragma unroll
    for (int q = 0; q < 4; q++) { v[q] = p[t + 128*q] * FSCALE; mx = fmaxf(mx, v[q]); }
    red[t] = mx; __syncthreads();
    for (int o = 64; o; o >>= 1) { if (t < o) red[t] = fmaxf(red[t], red[t+o]); __syncthreads(); }
    mx = red[0]; __syncthreads();
    float e[4]; float s = 0.f;
#pragma unroll
    for (int q = 0; q < 4; q++) { e[q] = expf(v[q] - mx); s += e[q]; }
    red[t] = s; __syncthreads();
    for (int o = 64; o; o >>= 1) { if (t < o) red[t] += red[t+o]; __syncthreads(); }
    s = red[0];
#pragma unroll
    for (int q = 0; q < 4; q++) p[t + 128*q] = e[q] / s;
}

// ---------------- selection: 3 byte-radix passes + exact cutoff -------------
__global__ void hist1_kernel() {
    __shared__ unsigned int h[256];
    int b = blockIdx.y;
    h[threadIdx.x] = 0u;
    __syncthreads();
    int base = b*NNE + blockIdx.x * (NNE/64);
    for (int i = threadIdx.x; i < NNE/64; i += 256) {
        unsigned int k = ford(g_W[base + i]);
        atomicAdd(&h[k >> 24], 1u);
    }
    __syncthreads();
    if (h[threadIdx.x]) atomicAdd(&g_hist[0*BB*256 + b*256 + threadIdx.x], h[threadIdx.x]);
}

__global__ void hist2_kernel() {
    int b = blockIdx.y;
    unsigned int hi = g_sel[b].hi;            // 8 bits
    int base = b*NNE + blockIdx.x * (NNE/64);
    for (int i = threadIdx.x; i < NNE/64; i += 256) {
        unsigned int k = ford(g_W[base + i]);
        if ((k >> 24) == hi) atomicAdd(&g_hist[1*BB*256 + b*256 + ((k >> 16) & 255u)], 1u);
    }
}

__global__ void hist3_kernel() {
    int b = blockIdx.y;
    unsigned int hi = g_sel[b].hi;            // 16 bits
    int base = b*NNE + blockIdx.x * (NNE/64);
    for (int i = threadIdx.x; i < NNE/64; i += 256) {
        unsigned int k = ford(g_W[base + i]);
        if ((k >> 16) == hi) atomicAdd(&g_hist[2*BB*256 + b*256 + ((k >> 8) & 255u)], 1u);
    }
}

__global__ void scan_kernel(int pass) {
    __shared__ unsigned int h[256];
    int b = blockIdx.x, t = threadIdx.x;
    h[t] = g_hist[pass*BB*256 + b*256 + t];
    __syncthreads();
    // suffix sum: h[t] = sum_{u>=t} count[u]
    for (int off = 1; off < 256; off <<= 1) {
        unsigned int add = (t + off < 256) ? h[t + off] : 0u;
        __syncthreads();
        h[t] += add;
        __syncthreads();
    }
    unsigned int need  = (pass == 0) ? (unsigned)KSEL : g_sel[b].need;
    unsigned int S     = h[t];
    unsigned int Snext = (t < 255) ? h[t + 1] : 0u;
    if (S >= need && Snext < need) {
        unsigned int hiprev = (pass == 0) ? 0u : g_sel[b].hi;
        g_sel[b].hi   = (hiprev << 8) | (unsigned int)t;
        g_sel[b].need = need - Snext;
    }
}

__global__ void collect_kernel() {
    int b = blockIdx.y;
    unsigned int hi = g_sel[b].hi;            // 24 bits
    int base = blockIdx.x * (NNE/64);
    for (int i = threadIdx.x; i < NNE/64; i += 256) {
        int idx = base + i;                   // flat index within batch
        unsigned int k = ford(g_W[b*NNE + idx]);
        if ((k >> 8) == hi) {
            unsigned int pos = atomicAdd(&g_cnt[b], 1u);
            if (pos < CAP)
                g_cand[b*CAP + pos] = ((unsigned long long)k << 32) | (unsigned int)idx;
        }
    }
}

__global__ void select_kernel() {
    __shared__ unsigned long long s[CAP];
    int b = blockIdx.x, t = threadIdx.x;
    unsigned int cnt = g_cnt[b]; if (cnt > CAP) cnt = CAP;
    for (unsigned int i = t; i < cnt; i += 256) s[i] = g_cand[b*CAP + i];
    __syncthreads();
    unsigned int need = g_sel[b].need;
    for (unsigned int i = t; i < cnt; i += 256) {
        unsigned long long k = s[i];
        unsigned int greater = 0;
        for (unsigned int j = 0; j < cnt; j++) greater += (s[j] > k);
        if (greater == need - 1) g_cut[b] = k;   // keys are unique: exactly one hit
    }
}

__global__ void mask_kernel(float* __restrict__ out) {
    int i = blockIdx.x * blockDim.x + threadIdx.x;
    if (i >= BB*NNE) return;
    int b = i >> 18;                           // NNE = 2^18
    unsigned long long key =
        ((unsigned long long)ford(g_W[i]) << 32) | (unsigned int)(i & (NNE - 1));
    out[i] = (key >= g_cut[b]) ? 1.0f : 0.0f;
}

// ---------------- launch ----------------------------------------------------
extern "C" void kernel_launch(void* const* d_in, const int* in_sizes, int n_in,
                              void* d_out, int out_size) {
    const float* x = (const float*)d_in[0];
    float* out = (float*)d_out;
    (void)in_sizes; (void)n_in; (void)out_size;

    zero_kernel<<<(3*BB*256 + 255)/256, 256>>>();
    stats_kernel<<<BB*NLEN/8, 256>>>(x);
    ecv_kernel<<<dim3(8, 8, BB), 256>>>(x);
    gemm_nt_kernel<<<dim3(8, 8, BB), 256>>>();
    softmax_kernel<<<BB*NLEN, 128>>>();
    gemm_nn_kernel<<<dim3(8, 8, BB), 256>>>();
    hist1_kernel<<<dim3(64, BB), 256>>>();
    scan_kernel<<<BB, 256>>>(0);
    hist2_kernel<<<dim3(64, BB), 256>>>();
    scan_kernel<<<BB, 256>>>(1);
    hist3_kernel<<<dim3(64, BB), 256>>>();
    scan_kernel<<<BB, 256>>>(2);
    collect_kernel<<<dim3(64, BB), 256>>>();
    select_kernel<<<BB, 256>>>();
    mask_kernel<<<(BB*NNE + 255)/256, 256>>>(out);
}

// round 2
// speedup vs baseline: 1.3783x; 1.3783x over previous
#include <cuda_runtime.h>
#include <math.h>

#define BB 8
#define NLEN 512
#define CDIM 128
#define NNE (NLEN*NLEN)          // 262144 = 2^18
#define KSEL 43690               // NNE//6
#define FSCALE 0.08838834764831845f
#define CAP 4096

// ---------------- scratch (static device globals; no allocation) -------------
static __device__ float g_E [BB*NNE];
static __device__ float g_Ch[BB*NNE];
static __device__ float g_V [BB*NNE];
static __device__ float g_L [BB*NNE];
static __device__ float g_W [BB*NNE];
static __device__ float g_sq[BB*NLEN];
static __device__ float g_mu[BB*NLEN];
static __device__ float g_ds[BB*NLEN];
static __device__ unsigned int g_hist[3*BB*256];
static __device__ unsigned int g_cnt[BB];
struct Sel { unsigned int hi; unsigned int need; };
static __device__ Sel g_sel[BB];
static __device__ unsigned long long g_cand[BB*CAP];
static __device__ unsigned long long g_cut[BB];

__device__ __forceinline__ unsigned int ford(float f) {
    unsigned int u = __float_as_uint(f);
    return (u & 0x80000000u) ? ~u : (u | 0x80000000u);   // monotone float->uint
}

// ---------------- zero per-iteration state ----------------------------------
__global__ void zero_kernel() {
    int t = blockIdx.x * blockDim.x + threadIdx.x;
    if (t < 3*BB*256) g_hist[t] = 0u;
    if (t < BB)       g_cnt[t]  = 0u;
}

// ---------------- per-row stats: sq = sum x^2, mu, ds = ||x - mu|| ----------
__global__ void stats_kernel(const float* __restrict__ x) {
    int row  = blockIdx.x * 8 + (threadIdx.x >> 5);     // 4096 rows
    int lane = threadIdx.x & 31;
    const float* xr = x + (size_t)row * CDIM;
    float v[4]; float s = 0.f, ss = 0.f;
#pragma unroll
    for (int i = 0; i < 4; i++) {
        v[i] = xr[lane + 32*i];
        s  += v[i];
        ss += v[i]*v[i];
    }
#pragma unroll
    for (int o = 16; o; o >>= 1) {
        s  += __shfl_xor_sync(0xffffffffu, s,  o);
        ss += __shfl_xor_sync(0xffffffffu, ss, o);
    }
    float mu = s * (1.0f/CDIM);
    float cs = 0.f;
#pragma unroll
    for (int i = 0; i < 4; i++) { float d = v[i]-mu; cs += d*d; }
#pragma unroll
    for (int o = 16; o; o >>= 1) cs += __shfl_xor_sync(0xffffffffu, cs, o);
    if (lane == 0) { g_mu[row] = mu; g_sq[row] = ss; g_ds[row] = sqrtf(cs); }
}

// ---------------- E / Ch / V tiles: symmetric, upper-triangle blocks --------
// 64x64 tile, 256 threads, 4x4 micro, smem pitch 68 so inner LDS are .128
__global__ void __launch_bounds__(256) ecv_kernel(const float* __restrict__ x) {
    __shared__ __align__(16) float Xn[64][68];
    __shared__ __align__(16) float Xm[64][68];
    int b  = blockIdx.y;
    // decode upper-triangle block index (36 blocks: bi<=bj)
    int r = blockIdx.x, bi = 0;
    while (r >= 8 - bi) { r -= 8 - bi; bi++; }
    int bj = bi + r;
    int i0 = bi * 64, j0 = bj * 64;
    int t  = threadIdx.x;
    int tx = t & 15, ty = t >> 4;
    const float* xb = x + (size_t)b * NLEN * CDIM;

    float g[4][4], ch[4][4];
#pragma unroll
    for (int i = 0; i < 4; i++)
#pragma unroll
        for (int j = 0; j < 4; j++) { g[i][j] = 0.f; ch[i][j] = 0.f; }

    for (int ph = 0; ph < 2; ph++) {
        int cbase = ph * 64;
#pragma unroll
        for (int it = 0; it < 4; it++) {
            int idx = t + 256*it;            // 0..1023 float4 slots
            int rr  = idx >> 4;              // 0..63
            int c4  = (idx & 15) * 4;        // 0..60
            float4 a = *(const float4*)&xb[(size_t)(i0+rr)*CDIM + cbase + c4];
            Xn[c4+0][rr] = a.x; Xn[c4+1][rr] = a.y; Xn[c4+2][rr] = a.z; Xn[c4+3][rr] = a.w;
            float4 m = *(const float4*)&xb[(size_t)(j0+rr)*CDIM + cbase + c4];
            Xm[c4+0][rr] = m.x; Xm[c4+1][rr] = m.y; Xm[c4+2][rr] = m.z; Xm[c4+3][rr] = m.w;
        }
        __syncthreads();
#pragma unroll 4
        for (int c = 0; c < 64; c++) {
            float a[4], bv[4];
            *(float4*)&a[0]  = *(const float4*)&Xn[c][ty*4];
            *(float4*)&bv[0] = *(const float4*)&Xm[c][tx*4];
#pragma unroll
            for (int i = 0; i < 4; i++)
#pragma unroll
                for (int j = 0; j < 4; j++) {
                    g[i][j]  = fmaf(a[i], bv[j], g[i][j]);
                    ch[i][j] = fmaxf(ch[i][j], fabsf(a[i] - bv[j]));
                }
        }
        __syncthreads();
    }

    int ib = b*NLEN + i0 + ty*4;
    int jb = b*NLEN + j0 + tx*4;
    float sqi[4], mui[4], dsi[4], sqj[4], muj[4], dsj[4];
#pragma unroll
    for (int q = 0; q < 4; q++) {
        sqi[q] = g_sq[ib+q]; mui[q] = g_mu[ib+q]; dsi[q] = g_ds[ib+q];
        sqj[q] = g_sq[jb+q]; muj[q] = g_mu[jb+q]; dsj[q] = g_ds[jb+q];
    }
    float e[4][4], v[4][4];
#pragma unroll
    for (int i = 0; i < 4; i++)
#pragma unroll
        for (int j = 0; j < 4; j++) {
            float d2 = sqi[i] + sqj[j] - 2.0f * g[i][j];
            e[i][j] = sqrtf(fmaxf(d2, 0.0f));
            float cov = g[i][j] - (float)CDIM * mui[i] * muj[j];
            float vv  = cov / (dsi[i] * dsj[j]);
            v[i][j] = fminf(fmaxf(vv, -1.0f), 1.0f);
        }
    // normal (row-major) stores
#pragma unroll
    for (int i = 0; i < 4; i++) {
        size_t off = (size_t)b*NNE + (size_t)(i0 + ty*4 + i)*NLEN + j0 + tx*4;
        *(float4*)&g_E [off] = make_float4(e[i][0], e[i][1], e[i][2], e[i][3]);
        *(float4*)&g_Ch[off] = make_float4(ch[i][0], ch[i][1], ch[i][2], ch[i][3]);
        *(float4*)&g_V [off] = make_float4(v[i][0], v[i][1], v[i][2], v[i][3]);
    }
    // mirror stores for off-diagonal blocks (symmetry)
    if (bi != bj) {
#pragma unroll
        for (int j = 0; j < 4; j++) {
            size_t rowoff = (size_t)b*NNE + (size_t)(j0 + tx*4 + j)*NLEN + i0 + ty*4;
#pragma unroll
            for (int i = 0; i < 4; i++) {
                g_E [rowoff + i] = e[i][j];
                g_Ch[rowoff + i] = ch[i][j];
                g_V [rowoff + i] = v[i][j];
            }
        }
    }
}

// ---------------- 128x128x8 double-buffered fp32 GEMM -----------------------
// TRANSB=true : C[n,m] = sum_k A[n,k] * B[m,k]  (NT)
// TRANSB=false: C[n,k] = sum_m A[n,m] * B[m,k]  (NN)
template<bool TRANSB>
__device__ __forceinline__ void gemm128_body(const float* __restrict__ A,
                                             const float* __restrict__ B,
                                             float* __restrict__ C) {
    __shared__ __align__(16) float As[2][8][132];
    __shared__ __align__(16) float Bs[2][8][132];
    int i0 = blockIdx.y * 128, j0 = blockIdx.x * 128;
    int t  = threadIdx.x;
    int tx = t & 15, ty = t >> 4;
    int ar = t >> 1, ac = (t & 1) * 4;      // A (and NT-B) loader: row, k-offset
    int bk = t >> 5, bc = (t & 31) * 4;     // NN-B loader: k-row, col-offset

    float acc[8][8];
#pragma unroll
    for (int i = 0; i < 8; i++)
#pragma unroll
        for (int j = 0; j < 8; j++) acc[i][j] = 0.f;

    float4 pa, pb;
    // prologue: tile kb=0
    pa = *(const float4*)&A[(size_t)(i0+ar)*NLEN + ac];
    if (TRANSB) pb = *(const float4*)&B[(size_t)(j0+ar)*NLEN + ac];
    else        pb = *(const float4*)&B[(size_t)bk*NLEN + j0 + bc];
    As[0][ac+0][ar]=pa.x; As[0][ac+1][ar]=pa.y; As[0][ac+2][ar]=pa.z; As[0][ac+3][ar]=pa.w;
    if (TRANSB) { Bs[0][ac+0][ar]=pb.x; Bs[0][ac+1][ar]=pb.y; Bs[0][ac+2][ar]=pb.z; Bs[0][ac+3][ar]=pb.w; }
    else        { *(float4*)&Bs[0][bk][bc] = pb; }
    __syncthreads();

    int cur = 0;
    for (int kb = 0; kb < NLEN; kb += 8) {
        bool notlast = (kb + 8 < NLEN);
        if (notlast) {
            pa = *(const float4*)&A[(size_t)(i0+ar)*NLEN + kb + 8 + ac];
            if (TRANSB) pb = *(const float4*)&B[(size_t)(j0+ar)*NLEN + kb + 8 + ac];
            else        pb = *(const float4*)&B[(size_t)(kb+8+bk)*NLEN + j0 + bc];
        }
#pragma unroll
        for (int kk = 0; kk < 8; kk++) {
            float a[8], b[8];
            *(float4*)&a[0] = *(const float4*)&As[cur][kk][ty*4];
            *(float4*)&a[4] = *(const float4*)&As[cur][kk][ty*4 + 64];
            *(float4*)&b[0] = *(const float4*)&Bs[cur][kk][tx*4];
            *(float4*)&b[4] = *(const float4*)&Bs[cur][kk][tx*4 + 64];
#pragma unroll
            for (int i = 0; i < 8; i++)
#pragma unroll
                for (int j = 0; j < 8; j++)
                    acc[i][j] = fmaf(a[i], b[j], acc[i][j]);
        }
        if (notlast) {
            int nb = cur ^ 1;
            As[nb][ac+0][ar]=pa.x; As[nb][ac+1][ar]=pa.y; As[nb][ac+2][ar]=pa.z; As[nb][ac+3][ar]=pa.w;
            if (TRANSB) { Bs[nb][ac+0][ar]=pb.x; Bs[nb][ac+1][ar]=pb.y; Bs[nb][ac+2][ar]=pb.z; Bs[nb][ac+3][ar]=pb.w; }
            else        { *(float4*)&Bs[nb][bk][bc] = pb; }
            __syncthreads();
            cur = nb;
        }
    }
#pragma unroll
    for (int gi = 0; gi < 2; gi++)
#pragma unroll
    for (int i = 0; i < 4; i++) {
        int row = i0 + gi*64 + ty*4 + i;
#pragma unroll
        for (int gj = 0; gj < 2; gj++) {
            float4 rv = make_float4(acc[gi*4+i][gj*4+0], acc[gi*4+i][gj*4+1],
                                    acc[gi*4+i][gj*4+2], acc[gi*4+i][gj*4+3]);
            *(float4*)&C[(size_t)row*NLEN + j0 + gj*64 + tx*4] = rv;
        }
    }
}

__global__ void __launch_bounds__(256) gemm_nt_kernel() {
    size_t o = (size_t)blockIdx.z * NNE;
    gemm128_body<true>(g_E + o, g_Ch + o, g_L + o);
}

__global__ void __launch_bounds__(256) gemm_nn_kernel() {
    size_t o = (size_t)blockIdx.z * NNE;
    gemm128_body<false>(g_L + o, g_V + o, g_W + o);
}

// ---------------- row softmax of L*SCALE (in place) -------------------------
__global__ void softmax_kernel() {
    __shared__ float red[128];
    int row = blockIdx.x;                          // 0..4095
    float* p = g_L + (size_t)row * NLEN;
    int t = threadIdx.x;
    float v[4]; float mx = -3.4e38f;
#pragma unroll
    for (int q = 0; q < 4; q++) { v[q] = p[t + 128*q] * FSCALE; mx = fmaxf(mx, v[q]); }
    red[t] = mx; __syncthreads();
    for (int o = 64; o; o >>= 1) { if (t < o) red[t] = fmaxf(red[t], red[t+o]); __syncthreads(); }
    mx = red[0]; __syncthreads();
    float e[4]; float s = 0.f;
#pragma unroll
    for (int q = 0; q < 4; q++) { e[q] = expf(v[q] - mx); s += e[q]; }
    red[t] = s; __syncthreads();
    for (int o = 64; o; o >>= 1) { if (t < o) red[t] += red[t+o]; __syncthreads(); }
    s = red[0];
#pragma unroll
    for (int q = 0; q < 4; q++) p[t + 128*q] = e[q] / s;
}

// ---------------- selection: 3 byte-radix passes + exact cutoff -------------
__global__ void hist1_kernel() {
    __shared__ unsigned int h[256];
    int b = blockIdx.y;
    h[threadIdx.x] = 0u;
    __syncthreads();
    int base = b*NNE + blockIdx.x * (NNE/64);
    for (int i = threadIdx.x; i < NNE/64; i += 256) {
        unsigned int k = ford(g_W[base + i]);
        atomicAdd(&h[k >> 24], 1u);
    }
    __syncthreads();
    if (h[threadIdx.x]) atomicAdd(&g_hist[0*BB*256 + b*256 + threadIdx.x], h[threadIdx.x]);
}

__global__ void hist2_kernel() {
    int b = blockIdx.y;
    unsigned int hi = g_sel[b].hi;            // 8 bits
    int base = b*NNE + blockIdx.x * (NNE/64);
    for (int i = threadIdx.x; i < NNE/64; i += 256) {
        unsigned int k = ford(g_W[base + i]);
        if ((k >> 24) == hi) atomicAdd(&g_hist[1*BB*256 + b*256 + ((k >> 16) & 255u)], 1u);
    }
}

__global__ void hist3_kernel() {
    int b = blockIdx.y;
    unsigned int hi = g_sel[b].hi;            // 16 bits
    int base = b*NNE + blockIdx.x * (NNE/64);
    for (int i = threadIdx.x; i < NNE/64; i += 256) {
        unsigned int k = ford(g_W[base + i]);
        if ((k >> 16) == hi) atomicAdd(&g_hist[2*BB*256 + b*256 + ((k >> 8) & 255u)], 1u);
    }
}

__global__ void scan_kernel(int pass) {
    __shared__ unsigned int h[256];
    int b = blockIdx.x, t = threadIdx.x;
    h[t] = g_hist[pass*BB*256 + b*256 + t];
    __syncthreads();
    // suffix sum: h[t] = sum_{u>=t} count[u]
    for (int off = 1; off < 256; off <<= 1) {
        unsigned int add = (t + off < 256) ? h[t + off] : 0u;
        __syncthreads();
        h[t] += add;
        __syncthreads();
    }
    unsigned int need  = (pass == 0) ? (unsigned)KSEL : g_sel[b].need;
    unsigned int S     = h[t];
    unsigned int Snext = (t < 255) ? h[t + 1] : 0u;
    if (S >= need && Snext < need) {
        unsigned int hiprev = (pass == 0) ? 0u : g_sel[b].hi;
        g_sel[b].hi   = (hiprev << 8) | (unsigned int)t;
        g_sel[b].need = need - Snext;
    }
}

__global__ void collect_kernel() {
    int b = blockIdx.y;
    unsigned int hi = g_sel[b].hi;            // 24 bits
    int base = blockIdx.x * (NNE/64);
    for (int i = threadIdx.x; i < NNE/64; i += 256) {
        int idx = base + i;                   // flat index within batch
        unsigned int k = ford(g_W[b*NNE + idx]);
        if ((k >> 8) == hi) {
            unsigned int pos = atomicAdd(&g_cnt[b], 1u);
            if (pos < CAP)
                g_cand[b*CAP + pos] = ((unsigned long long)k << 32) | (unsigned int)idx;
        }
    }
}

__global__ void select_kernel() {
    __shared__ unsigned long long s[CAP];
    int b = blockIdx.x, t = threadIdx.x;
    unsigned int cnt = g_cnt[b]; if (cnt > CAP) cnt = CAP;
    for (unsigned int i = t; i < cnt; i += 256) s[i] = g_cand[b*CAP + i];
    __syncthreads();
    unsigned int need = g_sel[b].need;
    for (unsigned int i = t; i < cnt; i += 256) {
        unsigned long long k = s[i];
        unsigned int greater = 0;
        for (unsigned int j = 0; j < cnt; j++) greater += (s[j] > k);
        if (greater == need - 1) g_cut[b] = k;   // keys are unique: exactly one hit
    }
}

__global__ void mask_kernel(float* __restrict__ out) {
    int i = blockIdx.x * blockDim.x + threadIdx.x;
    if (i >= BB*NNE) return;
    int b = i >> 18;                           // NNE = 2^18
    unsigned long long key =
        ((unsigned long long)ford(g_W[i]) << 32) | (unsigned int)(i & (NNE - 1));
    out[i] = (key >= g_cut[b]) ? 1.0f : 0.0f;
}

// ---------------- launch ----------------------------------------------------
extern "C" void kernel_launch(void* const* d_in, const int* in_sizes, int n_in,
                              void* d_out, int out_size) {
    const float* x = (const float*)d_in[0];
    float* out = (float*)d_out;
    (void)in_sizes; (void)n_in; (void)out_size;

    zero_kernel<<<(3*BB*256 + 255)/256, 256>>>();
    stats_kernel<<<BB*NLEN/8, 256>>>(x);
    ecv_kernel<<<dim3(36, BB), 256>>>(x);
    gemm_nt_kernel<<<dim3(4, 4, BB), 256>>>();
    softmax_kernel<<<BB*NLEN, 128>>>();
    gemm_nn_kernel<<<dim3(4, 4, BB), 256>>>();
    hist1_kernel<<<dim3(64, BB), 256>>>();
    scan_kernel<<<BB, 256>>>(0);
    hist2_kernel<<<dim3(64, BB), 256>>>();
    scan_kernel<<<BB, 256>>>(1);
    hist3_kernel<<<dim3(64, BB), 256>>>();
    scan_kernel<<<BB, 256>>>(2);
    collect_kernel<<<dim3(64, BB), 256>>>();
    select_kernel<<<BB, 256>>>();
    mask_kernel<<<(BB*NNE + 255)/256, 256>>>(out);
}

// round 4
// speedup vs baseline: 1.4368x; 1.0425x over previous
#include <cuda_runtime.h>
#include <math.h>

#define BB 8
#define NLEN 512
#define CDIM 128
#define NNE (NLEN*NLEN)          // 262144 = 2^18
#define KSEL 43690               // NNE//6
#define FSCALE 0.08838834764831845f
#define CAP 4096

typedef unsigned long long u64;

#define FMA2(d, a, b, c) \
    asm("fma.rn.f32x2 %0, %1, %2, %3;" : "=l"(d) : "l"(a), "l"(b), "l"(c))
#define PACK2(d, x) \
    asm("mov.b64 %0, {%1, %1};" : "=l"(d) : "f"(x))
#define UNPACK2(lo, hi, v) \
    asm("mov.b64 {%0, %1}, %2;" : "=f"(lo), "=f"(hi) : "l"(v))

// ---------------- scratch (static device globals; no allocation) -------------
static __device__ float g_E [BB*NNE];
static __device__ float g_Ch[BB*NNE];
static __device__ float g_V [BB*NNE];
static __device__ float g_L [BB*NNE];   // logits, then attn after softmax
static __device__ float g_W [BB*NNE];
static __device__ float g_sq[BB*NLEN];
static __device__ float g_mu[BB*NLEN];
static __device__ float g_ds[BB*NLEN];
static __device__ unsigned int g_hist[3*BB*256];
static __device__ unsigned int g_cnt[BB];
struct Sel { unsigned int hi; unsigned int need; };
static __device__ Sel g_sel[BB];
static __device__ unsigned long long g_cand[BB*CAP];
static __device__ unsigned long long g_cut[BB];

__device__ __forceinline__ unsigned int ford(float f) {
    unsigned int u = __float_as_uint(f);
    return (u & 0x80000000u) ? ~u : (u | 0x80000000u);   // monotone float->uint
}

// ---------------- zero per-iteration state ----------------------------------
__global__ void zero_kernel() {
    int t = blockIdx.x * blockDim.x + threadIdx.x;
    if (t < 3*BB*256) g_hist[t] = 0u;
    if (t < BB)       g_cnt[t]  = 0u;
}

// ---------------- per-row stats: sq = sum x^2, mu, ds = ||x - mu|| ----------
__global__ void stats_kernel(const float* __restrict__ x) {
    int row  = blockIdx.x * 8 + (threadIdx.x >> 5);     // 4096 rows
    int lane = threadIdx.x & 31;
    const float* xr = x + (size_t)row * CDIM;
    float v[4]; float s = 0.f, ss = 0.f;
#pragma unroll
    for (int i = 0; i < 4; i++) {
        v[i] = xr[lane + 32*i];
        s  += v[i];
        ss += v[i]*v[i];
    }
#pragma unroll
    for (int o = 16; o; o >>= 1) {
        s  += __shfl_xor_sync(0xffffffffu, s,  o);
        ss += __shfl_xor_sync(0xffffffffu, ss, o);
    }
    float mu = s * (1.0f/CDIM);
    float cs = 0.f;
#pragma unroll
    for (int i = 0; i < 4; i++) { float d = v[i]-mu; cs += d*d; }
#pragma unroll
    for (int o = 16; o; o >>= 1) cs += __shfl_xor_sync(0xffffffffu, cs, o);
    if (lane == 0) { g_mu[row] = mu; g_sq[row] = ss; g_ds[row] = sqrtf(cs); }
}

// ---------------- E / Ch / V tiles: symmetric, upper-triangle blocks --------
__global__ void __launch_bounds__(256) ecv_kernel(const float* __restrict__ x) {
    __shared__ __align__(16) float Xn[64][68];
    __shared__ __align__(16) float Xm[64][68];
    int b  = blockIdx.y;
    int r = blockIdx.x, bi = 0;
    while (r >= 8 - bi) { r -= 8 - bi; bi++; }
    int bj = bi + r;
    int i0 = bi * 64, j0 = bj * 64;
    int t  = threadIdx.x;
    int tx = t & 15, ty = t >> 4;
    const float* xb = x + (size_t)b * NLEN * CDIM;

    float g[4][4], ch[4][4];
#pragma unroll
    for (int i = 0; i < 4; i++)
#pragma unroll
        for (int j = 0; j < 4; j++) { g[i][j] = 0.f; ch[i][j] = 0.f; }

    for (int ph = 0; ph < 2; ph++) {
        int cbase = ph * 64;
#pragma unroll
        for (int it = 0; it < 4; it++) {
            int idx = t + 256*it;
            int rr  = idx >> 4;
            int c4  = (idx & 15) * 4;
            float4 a = *(const float4*)&xb[(size_t)(i0+rr)*CDIM + cbase + c4];
            Xn[c4+0][rr] = a.x; Xn[c4+1][rr] = a.y; Xn[c4+2][rr] = a.z; Xn[c4+3][rr] = a.w;
            float4 m = *(const float4*)&xb[(size_t)(j0+rr)*CDIM + cbase + c4];
            Xm[c4+0][rr] = m.x; Xm[c4+1][rr] = m.y; Xm[c4+2][rr] = m.z; Xm[c4+3][rr] = m.w;
        }
        __syncthreads();
#pragma unroll 4
        for (int c = 0; c < 64; c++) {
            float a[4], bv[4];
            *(float4*)&a[0]  = *(const float4*)&Xn[c][ty*4];
            *(float4*)&bv[0] = *(const float4*)&Xm[c][tx*4];
#pragma unroll
            for (int i = 0; i < 4; i++)
#pragma unroll
                for (int j = 0; j < 4; j++) {
                    g[i][j]  = fmaf(a[i], bv[j], g[i][j]);
                    ch[i][j] = fmaxf(ch[i][j], fabsf(a[i] - bv[j]));
                }
        }
        __syncthreads();
    }

    int ib = b*NLEN + i0 + ty*4;
    int jb = b*NLEN + j0 + tx*4;
    float sqi[4], mui[4], dsi[4], sqj[4], muj[4], dsj[4];
#pragma unroll
    for (int q = 0; q < 4; q++) {
        sqi[q] = g_sq[ib+q]; mui[q] = g_mu[ib+q]; dsi[q] = g_ds[ib+q];
        sqj[q] = g_sq[jb+q]; muj[q] = g_mu[jb+q]; dsj[q] = g_ds[jb+q];
    }
    float e[4][4], v[4][4];
#pragma unroll
    for (int i = 0; i < 4; i++)
#pragma unroll
        for (int j = 0; j < 4; j++) {
            float d2 = sqi[i] + sqj[j] - 2.0f * g[i][j];
            e[i][j] = sqrtf(fmaxf(d2, 0.0f));
            float cov = g[i][j] - (float)CDIM * mui[i] * muj[j];
            float vv  = cov / (dsi[i] * dsj[j]);
            v[i][j] = fminf(fmaxf(vv, -1.0f), 1.0f);
        }
#pragma unroll
    for (int i = 0; i < 4; i++) {
        size_t off = (size_t)b*NNE + (size_t)(i0 + ty*4 + i)*NLEN + j0 + tx*4;
        *(float4*)&g_E [off] = make_float4(e[i][0], e[i][1], e[i][2], e[i][3]);
        *(float4*)&g_Ch[off] = make_float4(ch[i][0], ch[i][1], ch[i][2], ch[i][3]);
        *(float4*)&g_V [off] = make_float4(v[i][0], v[i][1], v[i][2], v[i][3]);
    }
    if (bi != bj) {
#pragma unroll
        for (int j = 0; j < 4; j++) {
            size_t rowoff = (size_t)b*NNE + (size_t)(j0 + tx*4 + j)*NLEN + i0 + ty*4;
#pragma unroll
            for (int i = 0; i < 4; i++) {
                g_E [rowoff + i] = e[i][j];
                g_Ch[rowoff + i] = ch[i][j];
                g_V [rowoff + i] = v[i][j];
            }
        }
    }
}

// ------------- 128x128x8 double-buffered fp32 GEMM (FFMA2 packed) -----------
// Full K=512, sequential accumulation per output (bitwise == scalar fmaf chain)
// TRANSB=true : C[n,m] = sum_k A[n,k] * B[m,k]  (NT)
// TRANSB=false: C[n,k] = sum_m A[n,m] * B[m,k]  (NN)
template<bool TRANSB>
__device__ __forceinline__ void gemm128_body(const float* __restrict__ A,
                                             const float* __restrict__ B,
                                             float* __restrict__ C) {
    __shared__ __align__(16) float As[2][8][132];
    __shared__ __align__(16) float Bs[2][8][132];
    int i0 = blockIdx.y * 128, j0 = blockIdx.x * 128;
    int t  = threadIdx.x;
    int tx = t & 15, ty = t >> 4;
    int ar = t >> 1, ac = (t & 1) * 4;      // A (and NT-B) loader: row, k-offset
    int bk = t >> 5, bc = (t & 31) * 4;     // NN-B loader: k-row, col-offset

    // packed accumulators: acc2[i][jp] holds columns (2*jp, 2*jp+1) of row i
    u64 acc2[8][4];
    u64 zero2; { float z = 0.f; PACK2(zero2, z); }
#pragma unroll
    for (int i = 0; i < 8; i++)
#pragma unroll
        for (int j = 0; j < 4; j++) acc2[i][j] = zero2;

    float4 pa, pb;
    pa = *(const float4*)&A[(size_t)(i0+ar)*NLEN + ac];
    if (TRANSB) pb = *(const float4*)&B[(size_t)(j0+ar)*NLEN + ac];
    else        pb = *(const float4*)&B[(size_t)bk*NLEN + j0 + bc];
    As[0][ac+0][ar]=pa.x; As[0][ac+1][ar]=pa.y; As[0][ac+2][ar]=pa.z; As[0][ac+3][ar]=pa.w;
    if (TRANSB) { Bs[0][ac+0][ar]=pb.x; Bs[0][ac+1][ar]=pb.y; Bs[0][ac+2][ar]=pb.z; Bs[0][ac+3][ar]=pb.w; }
    else        { *(float4*)&Bs[0][bk][bc] = pb; }
    __syncthreads();

    int cur = 0;
    for (int kb = 0; kb < NLEN; kb += 8) {
        bool notlast = (kb + 8 < NLEN);
        if (notlast) {
            pa = *(const float4*)&A[(size_t)(i0+ar)*NLEN + kb + 8 + ac];
            if (TRANSB) pb = *(const float4*)&B[(size_t)(j0+ar)*NLEN + kb + 8 + ac];
            else        pb = *(const float4*)&B[(size_t)(kb+8+bk)*NLEN + j0 + bc];
        }
#pragma unroll
        for (int kk = 0; kk < 8; kk++) {
            float a[8];
            *(float4*)&a[0] = *(const float4*)&As[cur][kk][ty*4];
            *(float4*)&a[4] = *(const float4*)&As[cur][kk][ty*4 + 64];
            // b pairs straight out of the LDS.128 register quads
            ulonglong2 blo = *(const ulonglong2*)&Bs[cur][kk][tx*4];
            ulonglong2 bhi = *(const ulonglong2*)&Bs[cur][kk][tx*4 + 64];
#pragma unroll
            for (int i = 0; i < 8; i++) {
                u64 aa; PACK2(aa, a[i]);
                FMA2(acc2[i][0], aa, blo.x, acc2[i][0]);
                FMA2(acc2[i][1], aa, blo.y, acc2[i][1]);
                FMA2(acc2[i][2], aa, bhi.x, acc2[i][2]);
                FMA2(acc2[i][3], aa, bhi.y, acc2[i][3]);
            }
        }
        if (notlast) {
            int nb = cur ^ 1;
            As[nb][ac+0][ar]=pa.x; As[nb][ac+1][ar]=pa.y; As[nb][ac+2][ar]=pa.z; As[nb][ac+3][ar]=pa.w;
            if (TRANSB) { Bs[nb][ac+0][ar]=pb.x; Bs[nb][ac+1][ar]=pb.y; Bs[nb][ac+2][ar]=pb.z; Bs[nb][ac+3][ar]=pb.w; }
            else        { *(float4*)&Bs[nb][bk][bc] = pb; }
            __syncthreads();
            cur = nb;
        }
    }
#pragma unroll
    for (int gi = 0; gi < 2; gi++)
#pragma unroll
    for (int i = 0; i < 4; i++) {
        int row = i0 + gi*64 + ty*4 + i;
#pragma unroll
        for (int gj = 0; gj < 2; gj++) {
            float4 rv;
            UNPACK2(rv.x, rv.y, acc2[gi*4+i][gj*2+0]);
            UNPACK2(rv.z, rv.w, acc2[gi*4+i][gj*2+1]);
            *(float4*)&C[(size_t)row*NLEN + j0 + gj*64 + tx*4] = rv;
        }
    }
}

__global__ void __launch_bounds__(256) gemm_nt_kernel() {
    size_t o = (size_t)blockIdx.z * NNE;
    gemm128_body<true>(g_E + o, g_Ch + o, g_L + o);
}

__global__ void __launch_bounds__(256) gemm_nn_kernel() {
    size_t o = (size_t)blockIdx.z * NNE;
    gemm128_body<false>(g_L + o, g_V + o, g_W + o);
}

// ---------------- row softmax of L*SCALE (in place) -------------------------
__global__ void softmax_kernel() {
    __shared__ float red[128];
    int row = blockIdx.x;                          // 0..4095
    float* p = g_L + (size_t)row * NLEN;
    int t = threadIdx.x;
    float v[4]; float mx = -3.4e38f;
#pragma unroll
    for (int q = 0; q < 4; q++) { v[q] = p[t + 128*q] * FSCALE; mx = fmaxf(mx, v[q]); }
    red[t] = mx; __syncthreads();
    for (int o = 64; o; o >>= 1) { if (t < o) red[t] = fmaxf(red[t], red[t+o]); __syncthreads(); }
    mx = red[0]; __syncthreads();
    float e[4]; float s = 0.f;
#pragma unroll
    for (int q = 0; q < 4; q++) { e[q] = expf(v[q] - mx); s += e[q]; }
    red[t] = s; __syncthreads();
    for (int o = 64; o; o >>= 1) { if (t < o) red[t] += red[t+o]; __syncthreads(); }
    s = red[0];
#pragma unroll
    for (int q = 0; q < 4; q++) p[t + 128*q] = e[q] / s;
}

// ---------------- selection: 3 byte-radix passes + exact cutoff -------------
__global__ void hist1_kernel() {
    __shared__ unsigned int h[256];
    int b = blockIdx.y;
    h[threadIdx.x] = 0u;
    __syncthreads();
    int base = b*NNE + blockIdx.x * (NNE/64);
    for (int i = threadIdx.x; i < NNE/64; i += 256) {
        unsigned int k = ford(g_W[base + i]);
        atomicAdd(&h[k >> 24], 1u);
    }
    __syncthreads();
    if (h[threadIdx.x]) atomicAdd(&g_hist[0*BB*256 + b*256 + threadIdx.x], h[threadIdx.x]);
}

__global__ void hist2_kernel() {
    int b = blockIdx.y;
    unsigned int hi = g_sel[b].hi;            // 8 bits
    int base = b*NNE + blockIdx.x * (NNE/64);
    for (int i = threadIdx.x; i < NNE/64; i += 256) {
        unsigned int k = ford(g_W[base + i]);
        if ((k >> 24) == hi) atomicAdd(&g_hist[1*BB*256 + b*256 + ((k >> 16) & 255u)], 1u);
    }
}

__global__ void hist3_kernel() {
    int b = blockIdx.y;
    unsigned int hi = g_sel[b].hi;            // 16 bits
    int base = b*NNE + blockIdx.x * (NNE/64);
    for (int i = threadIdx.x; i < NNE/64; i += 256) {
        unsigned int k = ford(g_W[base + i]);
        if ((k >> 16) == hi) atomicAdd(&g_hist[2*BB*256 + b*256 + ((k >> 8) & 255u)], 1u);
    }
}

__global__ void scan_kernel(int pass) {
    __shared__ unsigned int h[256];
    int b = blockIdx.x, t = threadIdx.x;
    h[t] = g_hist[pass*BB*256 + b*256 + t];
    __syncthreads();
    for (int off = 1; off < 256; off <<= 1) {
        unsigned int add = (t + off < 256) ? h[t + off] : 0u;
        __syncthreads();
        h[t] += add;
        __syncthreads();
    }
    unsigned int need  = (pass == 0) ? (unsigned)KSEL : g_sel[b].need;
    unsigned int S     = h[t];
    unsigned int Snext = (t < 255) ? h[t + 1] : 0u;
    if (S >= need && Snext < need) {
        unsigned int hiprev = (pass == 0) ? 0u : g_sel[b].hi;
        g_sel[b].hi   = (hiprev << 8) | (unsigned int)t;
        g_sel[b].need = need - Snext;
    }
}

__global__ void collect_kernel() {
    int b = blockIdx.y;
    unsigned int hi = g_sel[b].hi;            // 24 bits
    int base = blockIdx.x * (NNE/64);
    for (int i = threadIdx.x; i < NNE/64; i += 256) {
        int idx = base + i;
        unsigned int k = ford(g_W[b*NNE + idx]);
        if ((k >> 8) == hi) {
            unsigned int pos = atomicAdd(&g_cnt[b], 1u);
            if (pos < CAP)
                g_cand[b*CAP + pos] = ((unsigned long long)k << 32) | (unsigned int)idx;
        }
    }
}

__global__ void select_kernel() {
    __shared__ unsigned long long s[CAP];
    int b = blockIdx.x, t = threadIdx.x;
    unsigned int cnt = g_cnt[b]; if (cnt > CAP) cnt = CAP;
    for (unsigned int i = t; i < cnt; i += 256) s[i] = g_cand[b*CAP + i];
    __syncthreads();
    unsigned int need = g_sel[b].need;
    for (unsigned int i = t; i < cnt; i += 256) {
        unsigned long long k = s[i];
        unsigned int greater = 0;
        for (unsigned int j = 0; j < cnt; j++) greater += (s[j] > k);
        if (greater == need - 1) g_cut[b] = k;
    }
}

__global__ void mask_kernel(float* __restrict__ out) {
    int i = blockIdx.x * blockDim.x + threadIdx.x;
    if (i >= BB*NNE) return;
    int b = i >> 18;                           // NNE = 2^18
    unsigned long long key =
        ((unsigned long long)ford(g_W[i]) << 32) | (unsigned int)(i & (NNE - 1));
    out[i] = (key >= g_cut[b]) ? 1.0f : 0.0f;
}

// ---------------- launch ----------------------------------------------------
extern "C" void kernel_launch(void* const* d_in, const int* in_sizes, int n_in,
                              void* d_out, int out_size) {
    const float* x = (const float*)d_in[0];
    float* out = (float*)d_out;
    (void)in_sizes; (void)n_in; (void)out_size;

    zero_kernel<<<(3*BB*256 + 255)/256, 256>>>();
    stats_kernel<<<BB*NLEN/8, 256>>>(x);
    ecv_kernel<<<dim3(36, BB), 256>>>(x);
    gemm_nt_kernel<<<dim3(4, 4, BB), 256>>>();
    softmax_kernel<<<BB*NLEN, 128>>>();
    gemm_nn_kernel<<<dim3(4, 4, BB), 256>>>();
    hist1_kernel<<<dim3(64, BB), 256>>>();
    scan_kernel<<<BB, 256>>>(0);
    hist2_kernel<<<dim3(64, BB), 256>>>();
    scan_kernel<<<BB, 256>>>(1);
    hist3_kernel<<<dim3(64, BB), 256>>>();
    scan_kernel<<<BB, 256>>>(2);
    collect_kernel<<<dim3(64, BB), 256>>>();
    select_kernel<<<BB, 256>>>();
    mask_kernel<<<(BB*NNE + 255)/256, 256>>>(out);
}